// round 2
// baseline (speedup 1.0000x reference)
#include <cuda_runtime.h>
#include <math.h>
#include <stdint.h>

#define N_F 100000
#define N_H 49152
#define NE  400000
#define TT  12
#define HH  64
#define AHD 128
#define NBLK ((N_F + 1023) / 1024)   // 98

// ---------------- device scratch (static, allocation-free) ----------------
__device__ int   g_deg_se[N_F];
__device__ int   g_deg_de[N_H];
__device__ int   g_deg_sd[N_H];
__device__ int   g_deg_dd[N_F];
__device__ float g_agg[N_H * TT];
__device__ float g_hproc[(size_t)TT * N_H * HH];   // (t, n, h) layout, c_sd folded in
__device__ int   g_off[N_F + 1];
__device__ int   g_cur[N_F];
__device__ int   g_csr[NE];
__device__ int   g_bsum[NBLK];
__device__ float g_score1[TT * N_F];
__device__ float g_s1o[TT * N_F];
__device__ float g_att[2 * AHD + 2];               // u[128], c2[128], k1, k2

// ---------------- helpers ----------------
__device__ __forceinline__ float fast_tanh(float x) {
    float y;
    asm("tanh.approx.f32 %0, %1;" : "=f"(y) : "f"(x));
    return y;
}
__device__ __forceinline__ float nan0(float x) {
    x = (x == x) ? x : 0.f;
    return fminf(fmaxf(x, -3.402823466e38f), 3.402823466e38f);
}
__device__ __forceinline__ float lrelu(float x) { return x > 0.f ? x : 0.01f * x; }

// packed fp32x2 fma (sm_100+ PTX only; ptxas never emits this from C++)
#define FMA2(d, a, b) asm("fma.rn.f32x2 %0, %1, %2, %0;" : "+l"(d) : "l"(a), "l"(b))
#define UNPK2(lo, hi, p) asm("mov.b64 {%0,%1}, %2;" : "=f"(lo), "=f"(hi) : "l"(p))

// ---------------- small kernels ----------------
__global__ void k_zero() {
    int i = blockIdx.x * blockDim.x + threadIdx.x;
    int stride = gridDim.x * blockDim.x;
    for (int j = i; j < N_F; j += stride) { g_deg_se[j] = 0; g_deg_dd[j] = 0; }
    for (int j = i; j < N_H; j += stride) { g_deg_de[j] = 0; g_deg_sd[j] = 0; }
    for (int j = i; j < N_H * TT; j += stride) g_agg[j] = 0.f;
}

__global__ void k_deg(const int* __restrict__ es, const int* __restrict__ ed,
                      const int* __restrict__ ds, const int* __restrict__ dd) {
    int e = blockIdx.x * blockDim.x + threadIdx.x;
    if (e >= NE) return;
    atomicAdd(&g_deg_se[es[e]], 1);
    atomicAdd(&g_deg_de[ed[e]], 1);
    atomicAdd(&g_deg_sd[ds[e]], 1);
    atomicAdd(&g_deg_dd[dd[e]], 1);
}

__global__ void k_enc(const float* __restrict__ feat, const int* __restrict__ es,
                      const int* __restrict__ ed) {
    int e = blockIdx.x * blockDim.x + threadIdx.x;
    if (e >= NE) return;
    int s = es[e], d = ed[e];
    float c = rsqrtf(fmaxf((float)g_deg_se[s], 1.f));
    const float4* fp = reinterpret_cast<const float4*>(feat + (size_t)s * 12);
    float4 v0 = fp[0], v1 = fp[1], v2 = fp[2];
    float vv[12] = {v0.x, v0.y, v0.z, v0.w, v1.x, v1.y, v1.z, v1.w, v2.x, v2.y, v2.z, v2.w};
    float* ap = g_agg + (size_t)d * TT;
#pragma unroll
    for (int t = 0; t < 12; t++) atomicAdd(ap + t, nan0(vv[t]) * c);
}

__global__ void k_hproc(const float* __restrict__ Wenc, const float* __restrict__ benc,
                        const float* __restrict__ Wproc, const float* __restrict__ bproc) {
    __shared__ float sWe[TT * HH], sBe[TT * HH], sWp[TT * TT], sBp[TT];
    int tid = threadIdx.x;
    for (int i = tid; i < TT * HH; i += 256) { sWe[i] = Wenc[i]; sBe[i] = benc[i]; }
    if (tid < TT * TT) sWp[tid] = Wproc[tid];
    if (tid < TT) sBp[tid] = bproc[tid];
    __syncthreads();
    int n = blockIdx.x * 4 + (tid >> 6);
    int h = tid & 63;
    if (n >= N_H) return;
    float cde = rsqrtf(fmaxf((float)g_deg_de[n], 1.f));
    float csd = rsqrtf(fmaxf((float)g_deg_sd[n], 1.f));
    float he[TT];
#pragma unroll
    for (int t = 0; t < TT; t++) {
        float s = g_agg[n * TT + t] * cde;
        he[t] = lrelu(fmaf(s, sWe[t * HH + h], sBe[t * HH + h]));
    }
#pragma unroll
    for (int o = 0; o < TT; o++) {
        float v = sBp[o];
#pragma unroll
        for (int t = 0; t < TT; t++) v = fmaf(he[t], sWp[t * TT + o], v);
        v = fmaxf(v, 0.f) * csd;
        g_hproc[((size_t)o * N_H + n) * HH + h] = v;
    }
}

// --- 3-phase parallel exclusive scan of g_deg_dd -> g_off / g_cur ---
__global__ void k_bsum() {
    __shared__ int sh[32];
    int b = blockIdx.x;
    int i = b * 1024 + threadIdx.x;
    int v = (i < N_F) ? g_deg_dd[i] : 0;
#pragma unroll
    for (int o = 16; o; o >>= 1) v += __shfl_down_sync(0xffffffffu, v, o);
    if ((threadIdx.x & 31) == 0) sh[threadIdx.x >> 5] = v;
    __syncthreads();
    if (threadIdx.x < 32) {
        int x = sh[threadIdx.x];
#pragma unroll
        for (int o = 16; o; o >>= 1) x += __shfl_down_sync(0xffffffffu, x, o);
        if (threadIdx.x == 0) g_bsum[b] = x;
    }
}

__global__ void k_bscan() {   // 1 block, 128 threads, NBLK<=128
    __shared__ int sh[128];
    int i = threadIdx.x;
    int v = (i < NBLK) ? g_bsum[i] : 0;
    sh[i] = v;
    __syncthreads();
    for (int o = 1; o < 128; o <<= 1) {
        int x = (i >= o) ? sh[i - o] : 0;
        __syncthreads();
        sh[i] += x;
        __syncthreads();
    }
    if (i < NBLK) g_bsum[i] = sh[i] - v;   // exclusive
}

__global__ void k_off() {
    __shared__ int sh[1024];
    int b = blockIdx.x, tid = threadIdx.x;
    int i = b * 1024 + tid;
    int v = (i < N_F) ? g_deg_dd[i] : 0;
    sh[tid] = v;
    __syncthreads();
    for (int o = 1; o < 1024; o <<= 1) {
        int x = (tid >= o) ? sh[tid - o] : 0;
        __syncthreads();
        sh[tid] += x;
        __syncthreads();
    }
    int base = g_bsum[b];
    if (i < N_F) {
        g_off[i + 1] = base + sh[tid];
        g_cur[i]     = base + sh[tid] - v;
    }
    if (i == 0) g_off[0] = 0;
}

__global__ void k_fill(const int* __restrict__ ds, const int* __restrict__ dd) {
    int e = blockIdx.x * blockDim.x + threadIdx.x;
    if (e >= NE) return;
    int pos = atomicAdd(&g_cur[dd[e]], 1);
    g_csr[pos] = ds[e];
}

__global__ void k_att(const float* __restrict__ Wlin, const float* __restrict__ blin,
                      const float* __restrict__ Wa1, const float* __restrict__ ba1,
                      const float* __restrict__ Wo) {
    int j = threadIdx.x;
    if (j < AHD) {
        float u = 0.f, c = 0.f;
        for (int h = 0; h < HH; h++) {
            float w = Wa1[h * AHD + j];
            u = fmaf(Wlin[h], w, u);
            c = fmaf(blin[h], w, c);
        }
        g_att[j] = u;
        g_att[AHD + j] = c + ba1[j];
    }
    if (j == 0) {
        float k1 = 0.f, k2 = 0.f;
        for (int h = 0; h < HH; h++) { k1 = fmaf(Wlin[h], Wo[h], k1); k2 = fmaf(blin[h], Wo[h], k2); }
        g_att[2 * AHD] = k1;
        g_att[2 * AHD + 1] = k2;
    }
}

// ---------------- heavy fused phase (f32x2 packed GEMMs) ----------------
// dyn smem layout (floats):
//   sAdup [64][132]  (8448)  A/space1, element dup: sAdup[k][2r]=sAdup[k][2r+1]
//   sW    [4096]             weight tile (row-major [k][j])
//   sB[64] sBa1[128] sWa2[128] sWo[64]
#define ADS 132
#define SMEM_PHASE ((64 * ADS + 4096 + 64 + 128 + 128 + 64) * 4)

__global__ void __launch_bounds__(256)
k_phase(const float* __restrict__ Wdec, const float* __restrict__ bdec,
        const float* __restrict__ Wa1, const float* __restrict__ ba1,
        const float* __restrict__ Wa2, const float* __restrict__ Wo) {
    extern __shared__ float dsm[];
    float* sAdup = dsm;
    float* sW    = dsm + 64 * ADS;
    float* sB    = sW + 4096;
    float* sBa1  = sB + 64;
    float* sWa2  = sBa1 + 128;
    float* sWo   = sWa2 + 128;

    int t = blockIdx.y;
    int row0 = blockIdx.x * 64;
    int tid = threadIdx.x;

    for (int i = tid; i < 4096; i += 256) sW[i] = Wdec[t * 4096 + i];
    if (tid < 64) { sB[tid] = bdec[t * 64 + tid]; sWo[tid] = Wo[tid]; }
    else if (tid >= 64 && tid < 192) { sBa1[tid - 64] = ba1[tid - 64]; sWa2[tid - 64] = Wa2[tid - 64]; }

    // gather: warp per 8 rows; writes duplicated A
    int wid = tid >> 5, lane = tid & 31;
    for (int r = wid * 8; r < wid * 8 + 8; ++r) {
        int f = row0 + r;
        float a0 = 0.f, a1v = 0.f;
        if (f < N_F) {
            int beg = g_off[f], end = g_off[f + 1];
            for (int e = beg; e < end; e++) {
                const float* hp = g_hproc + ((size_t)t * N_H + g_csr[e]) * HH;
                a0 += hp[lane];
                a1v += hp[lane + 32];
            }
            float cdd = rsqrtf(fmaxf((float)g_deg_dd[f], 1.f));
            a0 *= cdd; a1v *= cdd;
        }
        sAdup[lane * ADS + 2 * r] = a0;          sAdup[lane * ADS + 2 * r + 1] = a0;
        sAdup[(lane + 32) * ADS + 2 * r] = a1v;  sAdup[(lane + 32) * ADS + 2 * r + 1] = a1v;
    }
    __syncthreads();

    int tf = tid >> 4, th = tid & 15;   // rows tf*4..+3, cols th*4..+3

    // ---- GEMM1: space1 = leaky(A @ Wdec_t + b) ----
    unsigned long long acc2[4][2];
#pragma unroll
    for (int i = 0; i < 4; i++) { acc2[i][0] = 0ull; acc2[i][1] = 0ull; }
#pragma unroll 8
    for (int k = 0; k < 64; k++) {
        ulonglong2 ad01 = *(const ulonglong2*)&sAdup[k * ADS + tf * 8];
        ulonglong2 ad23 = *(const ulonglong2*)&sAdup[k * ADS + tf * 8 + 4];
        ulonglong2 bv   = *(const ulonglong2*)&sW[k * 64 + th * 4];
        FMA2(acc2[0][0], ad01.x, bv.x); FMA2(acc2[0][1], ad01.x, bv.y);
        FMA2(acc2[1][0], ad01.y, bv.x); FMA2(acc2[1][1], ad01.y, bv.y);
        FMA2(acc2[2][0], ad23.x, bv.x); FMA2(acc2[2][1], ad23.x, bv.y);
        FMA2(acc2[3][0], ad23.y, bv.x); FMA2(acc2[3][1], ad23.y, bv.y);
    }
    __syncthreads();
    // epilogue: bias + leaky, store duplicated (space1[r][j] -> sAdup[j][2r],[2r+1])
#pragma unroll
    for (int q = 0; q < 2; q++)
#pragma unroll
        for (int i = 0; i < 4; i++) {
            float lo, hi; UNPK2(lo, hi, acc2[i][q]);
            int j0 = th * 4 + 2 * q, j1 = j0 + 1;
            float v0 = lrelu(lo + sB[j0]);
            float v1 = lrelu(hi + sB[j1]);
            int r2 = 2 * (tf * 4 + i);
            sAdup[j0 * ADS + r2] = v0; sAdup[j0 * ADS + r2 + 1] = v0;
            sAdup[j1 * ADS + r2] = v1; sAdup[j1 * ADS + r2 + 1] = v1;
        }
    __syncthreads();

    // s1o = space1 @ Wo (thread per row; reads column 2*tid of dup array)
    if (tid < 64) {
        float v = 0.f;
#pragma unroll 8
        for (int k = 0; k < 64; k++) v = fmaf(sAdup[k * ADS + 2 * tid], sWo[k], v);
        int f = row0 + tid;
        if (f < N_F) g_s1o[t * N_F + f] = v;
    }

    // ---- GEMM2 in two 64-col halves of Wa1; score1 = tanh(.)@Wa2 ----
    float sc[4] = {0.f, 0.f, 0.f, 0.f};
    for (int half = 0; half < 2; ++half) {
        __syncthreads();
        for (int i2 = tid; i2 < 4096; i2 += 256) {
            int k = i2 >> 6, jj = i2 & 63;
            sW[i2] = Wa1[k * 128 + half * 64 + jj];
        }
        __syncthreads();
        unsigned long long z2[4][2];
#pragma unroll
        for (int i = 0; i < 4; i++) { z2[i][0] = 0ull; z2[i][1] = 0ull; }
#pragma unroll 8
        for (int k = 0; k < 64; k++) {
            ulonglong2 ad01 = *(const ulonglong2*)&sAdup[k * ADS + tf * 8];
            ulonglong2 ad23 = *(const ulonglong2*)&sAdup[k * ADS + tf * 8 + 4];
            ulonglong2 bv   = *(const ulonglong2*)&sW[k * 64 + th * 4];
            FMA2(z2[0][0], ad01.x, bv.x); FMA2(z2[0][1], ad01.x, bv.y);
            FMA2(z2[1][0], ad01.y, bv.x); FMA2(z2[1][1], ad01.y, bv.y);
            FMA2(z2[2][0], ad23.x, bv.x); FMA2(z2[2][1], ad23.x, bv.y);
            FMA2(z2[3][0], ad23.y, bv.x); FMA2(z2[3][1], ad23.y, bv.y);
        }
#pragma unroll
        for (int q = 0; q < 2; q++)
#pragma unroll
            for (int i = 0; i < 4; i++) {
                float lo, hi; UNPK2(lo, hi, z2[i][q]);
                int j0 = half * 64 + th * 4 + 2 * q;
                sc[i] = fmaf(fast_tanh(lo + sBa1[j0]),     sWa2[j0],     sc[i]);
                sc[i] = fmaf(fast_tanh(hi + sBa1[j0 + 1]), sWa2[j0 + 1], sc[i]);
            }
    }
    // reduce over 16 th-lanes (b_a2 cancels in 2-way softmax)
#pragma unroll
    for (int i = 0; i < 4; i++) {
        float v = sc[i];
        v += __shfl_down_sync(0xffffffffu, v, 8, 16);
        v += __shfl_down_sync(0xffffffffu, v, 4, 16);
        v += __shfl_down_sync(0xffffffffu, v, 2, 16);
        v += __shfl_down_sync(0xffffffffu, v, 1, 16);
        if (th == 0) {
            int f = row0 + tf * 4 + i;
            if (f < N_F) g_score1[t * N_F + f] = v;
        }
    }
}

// ---------------- fused 12-step scalar recurrence ----------------
__global__ void k_steps(const float* __restrict__ feat, const float* __restrict__ Wa2,
                        const float* __restrict__ bo, float* __restrict__ out) {
    __shared__ float su[128], sc2[128], sw2[128];
    int tid = threadIdx.x;
    if (tid < 128) { su[tid] = g_att[tid]; sc2[tid] = g_att[128 + tid]; sw2[tid] = Wa2[tid]; }
    __syncthreads();
    int f = blockIdx.x * blockDim.x + tid;
    if (f >= N_F) return;
    float y = nan0(feat[(size_t)f * 12 + 11]);
    float k1 = g_att[256], k2 = g_att[257], b0 = bo[0];
#pragma unroll 1
    for (int t = 0; t < TT; t++) {
        float s2 = 0.f;
#pragma unroll 16
        for (int j = 0; j < 128; j++)
            s2 = fmaf(fast_tanh(fmaf(y, su[j], sc2[j])), sw2[j], s2);
        float s1 = g_score1[t * N_F + f];
        float mx = fmaxf(s1, s2);
        float e1 = __expf(s1 - mx), e2 = __expf(s2 - mx);
        float a1 = e1 / (e1 + e2);
        float s2o = fmaf(y, k1, k2);
        y = fmaf(a1, g_s1o[t * N_F + f], (1.f - a1) * s2o) + b0;
        out[(size_t)t * N_F + f] = y;
    }
}

// ---------------- launch ----------------
extern "C" void kernel_launch(void* const* d_in, const int* in_sizes, int n_in,
                              void* d_out, int out_size) {
    const float* feat  = (const float*)d_in[0];
    const int*   es    = (const int*)d_in[1];
    const int*   ed    = (const int*)d_in[2];
    const int*   ds    = (const int*)d_in[3];
    const int*   dd    = (const int*)d_in[4];
    const float* Wenc  = (const float*)d_in[5];
    const float* benc  = (const float*)d_in[6];
    const float* Wproc = (const float*)d_in[7];
    const float* bproc = (const float*)d_in[8];
    const float* Wdec  = (const float*)d_in[9];
    const float* bdec  = (const float*)d_in[10];
    const float* Wlin  = (const float*)d_in[11];
    const float* blin  = (const float*)d_in[12];
    const float* Wa1   = (const float*)d_in[13];
    const float* ba1   = (const float*)d_in[14];
    const float* Wa2   = (const float*)d_in[15];
    /* ba2 = d_in[16] cancels in 2-way softmax */
    const float* Wo    = (const float*)d_in[17];
    const float* bo    = (const float*)d_in[18];
    float* out = (float*)d_out;

    cudaFuncSetAttribute(k_phase, cudaFuncAttributeMaxDynamicSharedMemorySize, SMEM_PHASE);

    k_zero<<<512, 256>>>();
    k_deg<<<(NE + 255) / 256, 256>>>(es, ed, ds, dd);
    k_enc<<<(NE + 255) / 256, 256>>>(feat, es, ed);
    k_bsum<<<NBLK, 1024>>>();
    k_bscan<<<1, 128>>>();
    k_off<<<NBLK, 1024>>>();
    k_fill<<<(NE + 255) / 256, 256>>>(ds, dd);
    k_hproc<<<(N_H + 3) / 4, 256>>>(Wenc, benc, Wproc, bproc);
    k_att<<<1, 128>>>(Wlin, blin, Wa1, ba1, Wo);
    dim3 pg((N_F + 63) / 64, TT);
    k_phase<<<pg, 256, SMEM_PHASE>>>(Wdec, bdec, Wa1, ba1, Wa2, Wo);
    k_steps<<<(N_F + 255) / 256, 256>>>(feat, Wa2, bo, out);
}

// round 3
// speedup vs baseline: 1.4365x; 1.4365x over previous
#include <cuda_runtime.h>
#include <math.h>
#include <stdint.h>

#define N_F 100000
#define N_H 49152
#define NE  400000
#define TT  12
#define HH  64
#define AHD 128
#define NBLK ((N_F + 1023) / 1024)   // 98

// ---------------- device scratch (static, allocation-free) ----------------
__device__ int   g_deg_se[N_F];
__device__ int   g_deg_de[N_H];
__device__ int   g_deg_sd[N_H];
__device__ int   g_deg_dd[N_F];
__device__ float g_agg[N_H * TT];
__device__ float g_hproc[(size_t)TT * N_H * HH];   // (t, n, h) layout, c_sd folded in
__device__ int   g_off[N_F + 1];
__device__ int   g_cur[N_F];
__device__ int   g_csr[NE];
__device__ int   g_bsum[NBLK];
__device__ float g_score1[TT * N_F];
__device__ float g_s1o[TT * N_F];
__device__ float g_att[2 * AHD + 2];               // u[128], c2[128], k1, k2

// ---------------- helpers ----------------
__device__ __forceinline__ float fast_tanh(float x) {
    float y;
    asm("tanh.approx.f32 %0, %1;" : "=f"(y) : "f"(x));
    return y;
}
__device__ __forceinline__ float nan0(float x) {
    x = (x == x) ? x : 0.f;
    return fminf(fmaxf(x, -3.402823466e38f), 3.402823466e38f);
}
__device__ __forceinline__ float lrelu(float x) { return x > 0.f ? x : 0.01f * x; }
__device__ __forceinline__ float to_tf32(float x) {
    unsigned u;
    asm("cvt.rna.tf32.f32 %0, %1;" : "=r"(u) : "f"(x));
    return __uint_as_float(u);
}
__device__ __forceinline__ void mma_tf32(float& c0, float& c1, float& c2, float& c3,
                                         float a0, float a1, float a2, float a3,
                                         float b0, float b1) {
    asm("mma.sync.aligned.m16n8k8.row.col.f32.tf32.tf32.f32 "
        "{%0,%1,%2,%3},{%4,%5,%6,%7},{%8,%9},{%0,%1,%2,%3};"
        : "+f"(c0), "+f"(c1), "+f"(c2), "+f"(c3)
        : "r"(__float_as_uint(a0)), "r"(__float_as_uint(a1)),
          "r"(__float_as_uint(a2)), "r"(__float_as_uint(a3)),
          "r"(__float_as_uint(b0)), "r"(__float_as_uint(b1)));
}

// ---------------- small kernels ----------------
__global__ void k_zero() {
    int i = blockIdx.x * blockDim.x + threadIdx.x;
    int stride = gridDim.x * blockDim.x;
    for (int j = i; j < N_F; j += stride) { g_deg_se[j] = 0; g_deg_dd[j] = 0; }
    for (int j = i; j < N_H; j += stride) { g_deg_de[j] = 0; g_deg_sd[j] = 0; }
    for (int j = i; j < N_H * TT; j += stride) g_agg[j] = 0.f;
}

__global__ void k_deg(const int* __restrict__ es, const int* __restrict__ ed,
                      const int* __restrict__ ds, const int* __restrict__ dd) {
    int e = blockIdx.x * blockDim.x + threadIdx.x;
    if (e >= NE) return;
    atomicAdd(&g_deg_se[es[e]], 1);
    atomicAdd(&g_deg_de[ed[e]], 1);
    atomicAdd(&g_deg_sd[ds[e]], 1);
    atomicAdd(&g_deg_dd[dd[e]], 1);
}

__global__ void k_enc(const float* __restrict__ feat, const int* __restrict__ es,
                      const int* __restrict__ ed) {
    int e = blockIdx.x * blockDim.x + threadIdx.x;
    if (e >= NE) return;
    int s = es[e], d = ed[e];
    float c = rsqrtf(fmaxf((float)g_deg_se[s], 1.f));
    const float4* fp = reinterpret_cast<const float4*>(feat + (size_t)s * 12);
    float4 v0 = fp[0], v1 = fp[1], v2 = fp[2];
    float vv[12] = {v0.x, v0.y, v0.z, v0.w, v1.x, v1.y, v1.z, v1.w, v2.x, v2.y, v2.z, v2.w};
    float* ap = g_agg + (size_t)d * TT;
#pragma unroll
    for (int t = 0; t < 12; t++) atomicAdd(ap + t, nan0(vv[t]) * c);
}

__global__ void k_hproc(const float* __restrict__ Wenc, const float* __restrict__ benc,
                        const float* __restrict__ Wproc, const float* __restrict__ bproc) {
    __shared__ float sWe[TT * HH], sBe[TT * HH], sWp[TT * TT], sBp[TT];
    int tid = threadIdx.x;
    for (int i = tid; i < TT * HH; i += 256) { sWe[i] = Wenc[i]; sBe[i] = benc[i]; }
    if (tid < TT * TT) sWp[tid] = Wproc[tid];
    if (tid < TT) sBp[tid] = bproc[tid];
    __syncthreads();
    int n = blockIdx.x * 4 + (tid >> 6);
    int h = tid & 63;
    if (n >= N_H) return;
    float cde = rsqrtf(fmaxf((float)g_deg_de[n], 1.f));
    float csd = rsqrtf(fmaxf((float)g_deg_sd[n], 1.f));
    float he[TT];
#pragma unroll
    for (int t = 0; t < TT; t++) {
        float s = g_agg[n * TT + t] * cde;
        he[t] = lrelu(fmaf(s, sWe[t * HH + h], sBe[t * HH + h]));
    }
#pragma unroll
    for (int o = 0; o < TT; o++) {
        float v = sBp[o];
#pragma unroll
        for (int t = 0; t < TT; t++) v = fmaf(he[t], sWp[t * TT + o], v);
        v = fmaxf(v, 0.f) * csd;
        g_hproc[((size_t)o * N_H + n) * HH + h] = v;
    }
}

// --- 3-phase parallel exclusive scan of g_deg_dd -> g_off / g_cur ---
__global__ void k_bsum() {
    __shared__ int sh[32];
    int b = blockIdx.x;
    int i = b * 1024 + threadIdx.x;
    int v = (i < N_F) ? g_deg_dd[i] : 0;
#pragma unroll
    for (int o = 16; o; o >>= 1) v += __shfl_down_sync(0xffffffffu, v, o);
    if ((threadIdx.x & 31) == 0) sh[threadIdx.x >> 5] = v;
    __syncthreads();
    if (threadIdx.x < 32) {
        int x = sh[threadIdx.x];
#pragma unroll
        for (int o = 16; o; o >>= 1) x += __shfl_down_sync(0xffffffffu, x, o);
        if (threadIdx.x == 0) g_bsum[b] = x;
    }
}

__global__ void k_bscan() {   // 1 block, 128 threads, NBLK<=128
    __shared__ int sh[128];
    int i = threadIdx.x;
    int v = (i < NBLK) ? g_bsum[i] : 0;
    sh[i] = v;
    __syncthreads();
    for (int o = 1; o < 128; o <<= 1) {
        int x = (i >= o) ? sh[i - o] : 0;
        __syncthreads();
        sh[i] += x;
        __syncthreads();
    }
    if (i < NBLK) g_bsum[i] = sh[i] - v;   // exclusive
}

__global__ void k_off() {
    __shared__ int sh[1024];
    int b = blockIdx.x, tid = threadIdx.x;
    int i = b * 1024 + tid;
    int v = (i < N_F) ? g_deg_dd[i] : 0;
    sh[tid] = v;
    __syncthreads();
    for (int o = 1; o < 1024; o <<= 1) {
        int x = (tid >= o) ? sh[tid - o] : 0;
        __syncthreads();
        sh[tid] += x;
        __syncthreads();
    }
    int base = g_bsum[b];
    if (i < N_F) {
        g_off[i + 1] = base + sh[tid];
        g_cur[i]     = base + sh[tid] - v;
    }
    if (i == 0) g_off[0] = 0;
}

__global__ void k_fill(const int* __restrict__ ds, const int* __restrict__ dd) {
    int e = blockIdx.x * blockDim.x + threadIdx.x;
    if (e >= NE) return;
    int pos = atomicAdd(&g_cur[dd[e]], 1);
    g_csr[pos] = ds[e];
}

__global__ void k_att(const float* __restrict__ Wlin, const float* __restrict__ blin,
                      const float* __restrict__ Wa1, const float* __restrict__ ba1,
                      const float* __restrict__ Wo) {
    int j = threadIdx.x;
    if (j < AHD) {
        float u = 0.f, c = 0.f;
        for (int h = 0; h < HH; h++) {
            float w = Wa1[h * AHD + j];
            u = fmaf(Wlin[h], w, u);
            c = fmaf(blin[h], w, c);
        }
        g_att[j] = u;
        g_att[AHD + j] = c + ba1[j];
    }
    if (j == 0) {
        float k1 = 0.f, k2 = 0.f;
        for (int h = 0; h < HH; h++) { k1 = fmaf(Wlin[h], Wo[h], k1); k2 = fmaf(blin[h], Wo[h], k2); }
        g_att[2 * AHD] = k1;
        g_att[2 * AHD + 1] = k2;
    }
}

// ---------------- heavy fused phase (tf32 tensor-core GEMMs) ----------------
// dyn smem (floats):
//   sA  [64][68]  A / space1 (tf32-rounded), row-major stride 68
//   sWd [64][68]  Wdec_t  [k][n]
//   sWa [64][136] Wa1     [k][n]
//   sB[64] sBa1[128] sWa2[128] sWo[64] sSc[64]
#define SA_S 68
#define SW_S 68
#define SWA_S 136
#define SMEM_PHASE ((64*SA_S + 64*SW_S + 64*SWA_S + 64 + 128 + 128 + 64 + 64) * 4)

__global__ void __launch_bounds__(256)
k_phase(const float* __restrict__ Wdec, const float* __restrict__ bdec,
        const float* __restrict__ Wa1, const float* __restrict__ ba1,
        const float* __restrict__ Wa2, const float* __restrict__ Wo) {
    extern __shared__ float dsm[];
    float* sA   = dsm;
    float* sWd  = sA + 64 * SA_S;
    float* sWa  = sWd + 64 * SW_S;
    float* sB   = sWa + 64 * SWA_S;
    float* sBa1 = sB + 64;
    float* sWa2 = sBa1 + 128;
    float* sWo  = sWa2 + 128;
    float* sSc  = sWo + 64;

    int t = blockIdx.y;
    int row0 = blockIdx.x * 64;
    int tid = threadIdx.x;

    // weight fills (tf32-rounded for MMA operands)
    for (int i = tid; i < 4096; i += 256) {
        int k = i >> 6, n = i & 63;
        sWd[k * SW_S + n] = to_tf32(Wdec[t * 4096 + i]);
    }
    for (int i = tid; i < 8192; i += 256) {
        int k = i >> 7, n = i & 127;
        sWa[k * SWA_S + n] = to_tf32(Wa1[i]);
    }
    if (tid < 64) { sB[tid] = bdec[t * 64 + tid]; sWo[tid] = Wo[tid]; sSc[tid] = 0.f; }
    else if (tid < 192) { sBa1[tid - 64] = ba1[tid - 64]; sWa2[tid - 64] = Wa2[tid - 64]; }

    // gather (warp per 8 rows, 4-way edge unroll for MLP); c_dd folded in
    int w = tid >> 5, lane = tid & 31;
    const float* hb = g_hproc + (size_t)t * N_H * HH;
    for (int r = w * 8; r < w * 8 + 8; ++r) {
        int f = row0 + r;
        float a0 = 0.f, a1v = 0.f;
        if (f < N_F) {
            int e = g_off[f], end = g_off[f + 1];
            for (; e + 4 <= end; e += 4) {
                int i0 = g_csr[e], i1 = g_csr[e + 1], i2 = g_csr[e + 2], i3 = g_csr[e + 3];
                const float* p0 = hb + (size_t)i0 * HH;
                const float* p1 = hb + (size_t)i1 * HH;
                const float* p2 = hb + (size_t)i2 * HH;
                const float* p3 = hb + (size_t)i3 * HH;
                float x0 = p0[lane], x1 = p1[lane], x2 = p2[lane], x3 = p3[lane];
                float y0 = p0[lane + 32], y1 = p1[lane + 32], y2 = p2[lane + 32], y3 = p3[lane + 32];
                a0  += (x0 + x1) + (x2 + x3);
                a1v += (y0 + y1) + (y2 + y3);
            }
            for (; e < end; e++) {
                const float* p = hb + (size_t)g_csr[e] * HH;
                a0 += p[lane];
                a1v += p[lane + 32];
            }
            float cdd = rsqrtf(fmaxf((float)g_deg_dd[f], 1.f));
            a0 *= cdd; a1v *= cdd;
        }
        sA[r * SA_S + lane] = to_tf32(a0);
        sA[r * SA_S + lane + 32] = to_tf32(a1v);
    }
    __syncthreads();

    // warp tiling: band r0 = (w&3)*16; column half colsel = w>>2
    int g = lane >> 2, q = lane & 3;
    int r0 = (w & 3) * 16;
    int colsel = w >> 2;

    // ---- GEMM1: space1 = leaky(A @ Wdec_t + b), 4 n-tiles per warp ----
    float c1[4][4];
#pragma unroll
    for (int tn = 0; tn < 4; tn++)
#pragma unroll
        for (int i = 0; i < 4; i++) c1[tn][i] = 0.f;
#pragma unroll
    for (int ks = 0; ks < 8; ks++) {
        int k0 = ks * 8;
        float a0 = sA[(r0 + g) * SA_S + k0 + q];
        float a1 = sA[(r0 + g + 8) * SA_S + k0 + q];
        float a2 = sA[(r0 + g) * SA_S + k0 + q + 4];
        float a3 = sA[(r0 + g + 8) * SA_S + k0 + q + 4];
#pragma unroll
        for (int tn = 0; tn < 4; tn++) {
            int nb = colsel * 32 + tn * 8;
            float b0 = sWd[(k0 + q) * SW_S + nb + g];
            float b1 = sWd[(k0 + q + 4) * SW_S + nb + g];
            mma_tf32(c1[tn][0], c1[tn][1], c1[tn][2], c1[tn][3], a0, a1, a2, a3, b0, b1);
        }
    }
    __syncthreads();
    // epilogue: bias + leaky -> space1 into sA (tf32-rounded)
#pragma unroll
    for (int tn = 0; tn < 4; tn++) {
        int col0 = colsel * 32 + tn * 8 + 2 * q;
        sA[(r0 + g) * SA_S + col0]         = to_tf32(lrelu(c1[tn][0] + sB[col0]));
        sA[(r0 + g) * SA_S + col0 + 1]     = to_tf32(lrelu(c1[tn][1] + sB[col0 + 1]));
        sA[(r0 + g + 8) * SA_S + col0]     = to_tf32(lrelu(c1[tn][2] + sB[col0]));
        sA[(r0 + g + 8) * SA_S + col0 + 1] = to_tf32(lrelu(c1[tn][3] + sB[col0 + 1]));
    }
    __syncthreads();

    // s1o = space1 @ Wo (thread per row)
    if (tid < 64) {
        float v = 0.f;
#pragma unroll 8
        for (int k = 0; k < 64; k++) v = fmaf(sA[tid * SA_S + k], sWo[k], v);
        int f = row0 + tid;
        if (f < N_F) g_s1o[t * N_F + f] = v;
    }

    // ---- GEMM2: z = space1 @ Wa1 (64 cols per warp in 2 passes of 4 tiles) ----
    float sc0 = 0.f, sc1 = 0.f;
#pragma unroll
    for (int pass = 0; pass < 2; ++pass) {
        float z[4][4];
#pragma unroll
        for (int tn = 0; tn < 4; tn++)
#pragma unroll
            for (int i = 0; i < 4; i++) z[tn][i] = 0.f;
#pragma unroll
        for (int ks = 0; ks < 8; ks++) {
            int k0 = ks * 8;
            float a0 = sA[(r0 + g) * SA_S + k0 + q];
            float a1 = sA[(r0 + g + 8) * SA_S + k0 + q];
            float a2 = sA[(r0 + g) * SA_S + k0 + q + 4];
            float a3 = sA[(r0 + g + 8) * SA_S + k0 + q + 4];
#pragma unroll
            for (int tn = 0; tn < 4; tn++) {
                int cb = colsel * 64 + pass * 32 + tn * 8;
                float b0 = sWa[(k0 + q) * SWA_S + cb + g];
                float b1 = sWa[(k0 + q + 4) * SWA_S + cb + g];
                mma_tf32(z[tn][0], z[tn][1], z[tn][2], z[tn][3], a0, a1, a2, a3, b0, b1);
            }
        }
#pragma unroll
        for (int tn = 0; tn < 4; tn++) {
            int col0 = colsel * 64 + pass * 32 + tn * 8 + 2 * q;
            sc0 = fmaf(fast_tanh(z[tn][0] + sBa1[col0]),     sWa2[col0],     sc0);
            sc0 = fmaf(fast_tanh(z[tn][1] + sBa1[col0 + 1]), sWa2[col0 + 1], sc0);
            sc1 = fmaf(fast_tanh(z[tn][2] + sBa1[col0]),     sWa2[col0],     sc1);
            sc1 = fmaf(fast_tanh(z[tn][3] + sBa1[col0 + 1]), sWa2[col0 + 1], sc1);
        }
    }
    // reduce over the 4 lanes of each group (cols), then combine the 2 col-half warps
    sc0 += __shfl_down_sync(0xffffffffu, sc0, 2, 4);
    sc0 += __shfl_down_sync(0xffffffffu, sc0, 1, 4);
    sc1 += __shfl_down_sync(0xffffffffu, sc1, 2, 4);
    sc1 += __shfl_down_sync(0xffffffffu, sc1, 1, 4);
    if (q == 0) {
        atomicAdd(&sSc[r0 + g], sc0);
        atomicAdd(&sSc[r0 + g + 8], sc1);
    }
    __syncthreads();
    if (tid < 64) {
        int f = row0 + tid;
        if (f < N_F) g_score1[t * N_F + f] = sSc[tid];  // b_a2 cancels in 2-way softmax
    }
}

// ---------------- fused 12-step scalar recurrence ----------------
__global__ void k_steps(const float* __restrict__ feat, const float* __restrict__ Wa2,
                        const float* __restrict__ bo, float* __restrict__ out) {
    __shared__ float su[128], sc2[128], sw2[128];
    int tid = threadIdx.x;
    if (tid < 128) { su[tid] = g_att[tid]; sc2[tid] = g_att[128 + tid]; sw2[tid] = Wa2[tid]; }
    __syncthreads();
    int f = blockIdx.x * blockDim.x + tid;
    if (f >= N_F) return;
    float y = nan0(feat[(size_t)f * 12 + 11]);
    float k1 = g_att[256], k2 = g_att[257], b0 = bo[0];
#pragma unroll 1
    for (int t = 0; t < TT; t++) {
        float s2 = 0.f;
#pragma unroll 16
        for (int j = 0; j < 128; j++)
            s2 = fmaf(fast_tanh(fmaf(y, su[j], sc2[j])), sw2[j], s2);
        float s1 = g_score1[t * N_F + f];
        float mx = fmaxf(s1, s2);
        float e1 = __expf(s1 - mx), e2 = __expf(s2 - mx);
        float a1 = e1 / (e1 + e2);
        float s2o = fmaf(y, k1, k2);
        y = fmaf(a1, g_s1o[t * N_F + f], (1.f - a1) * s2o) + b0;
        out[(size_t)t * N_F + f] = y;
    }
}

// ---------------- launch ----------------
extern "C" void kernel_launch(void* const* d_in, const int* in_sizes, int n_in,
                              void* d_out, int out_size) {
    const float* feat  = (const float*)d_in[0];
    const int*   es    = (const int*)d_in[1];
    const int*   ed    = (const int*)d_in[2];
    const int*   ds    = (const int*)d_in[3];
    const int*   dd    = (const int*)d_in[4];
    const float* Wenc  = (const float*)d_in[5];
    const float* benc  = (const float*)d_in[6];
    const float* Wproc = (const float*)d_in[7];
    const float* bproc = (const float*)d_in[8];
    const float* Wdec  = (const float*)d_in[9];
    const float* bdec  = (const float*)d_in[10];
    const float* Wlin  = (const float*)d_in[11];
    const float* blin  = (const float*)d_in[12];
    const float* Wa1   = (const float*)d_in[13];
    const float* ba1   = (const float*)d_in[14];
    const float* Wa2   = (const float*)d_in[15];
    /* ba2 = d_in[16] cancels in 2-way softmax */
    const float* Wo    = (const float*)d_in[17];
    const float* bo    = (const float*)d_in[18];
    float* out = (float*)d_out;

    cudaFuncSetAttribute(k_phase, cudaFuncAttributeMaxDynamicSharedMemorySize, SMEM_PHASE);

    k_zero<<<512, 256>>>();
    k_deg<<<(NE + 255) / 256, 256>>>(es, ed, ds, dd);
    k_enc<<<(NE + 255) / 256, 256>>>(feat, es, ed);
    k_bsum<<<NBLK, 1024>>>();
    k_bscan<<<1, 128>>>();
    k_off<<<NBLK, 1024>>>();
    k_fill<<<(NE + 255) / 256, 256>>>(ds, dd);
    k_hproc<<<(N_H + 3) / 4, 256>>>(Wenc, benc, Wproc, bproc);
    k_att<<<1, 128>>>(Wlin, blin, Wa1, ba1, Wo);
    dim3 pg((N_F + 63) / 64, TT);
    k_phase<<<pg, 256, SMEM_PHASE>>>(Wdec, bdec, Wa1, ba1, Wa2, Wo);
    k_steps<<<(N_F + 255) / 256, 256>>>(feat, Wa2, bo, out);
}

// round 4
// speedup vs baseline: 1.6283x; 1.1335x over previous
#include <cuda_runtime.h>
#include <cuda_fp16.h>
#include <math.h>
#include <stdint.h>

#define N_F 100000
#define N_H 49152
#define NE  400000
#define TT  12
#define HH  64
#define AHD 128
#define NBLK ((N_F + 1023) / 1024)   // 98

// ---------------- device scratch (static, allocation-free) ----------------
__device__ int     g_deg_se[N_F];
__device__ int     g_deg_de[N_H];
__device__ int     g_deg_sd[N_H];
__device__ int     g_deg_dd[N_F];
__device__ float   g_agg[N_H * TT];
__device__ __half2 g_hp[(size_t)TT * N_H * 32];   // (t, n, h/2) fp16 pairs, c_sd folded in
__device__ int     g_off[N_F + 1];
__device__ int     g_cur[N_F];
__device__ int     g_csr[NE];
__device__ int     g_bsum[NBLK];
__device__ float   g_score1[TT * N_F];
__device__ float   g_s1o[TT * N_F];
__device__ float   g_att[2 * AHD + 2];            // u[128], c2[128], k1, k2

// ---------------- helpers ----------------
__device__ __forceinline__ float fast_tanh(float x) {
    float y;
    asm("tanh.approx.f32 %0, %1;" : "=f"(y) : "f"(x));
    return y;
}
__device__ __forceinline__ float nan0(float x) {
    x = (x == x) ? x : 0.f;
    return fminf(fmaxf(x, -3.402823466e38f), 3.402823466e38f);
}
__device__ __forceinline__ float lrelu(float x) { return x > 0.f ? x : 0.01f * x; }
__device__ __forceinline__ float to_tf32(float x) {
    unsigned u;
    asm("cvt.rna.tf32.f32 %0, %1;" : "=r"(u) : "f"(x));
    return __uint_as_float(u);
}
__device__ __forceinline__ void mma_tf32(float& c0, float& c1, float& c2, float& c3,
                                         float a0, float a1, float a2, float a3,
                                         float b0, float b1) {
    asm("mma.sync.aligned.m16n8k8.row.col.f32.tf32.tf32.f32 "
        "{%0,%1,%2,%3},{%4,%5,%6,%7},{%8,%9},{%0,%1,%2,%3};"
        : "+f"(c0), "+f"(c1), "+f"(c2), "+f"(c3)
        : "r"(__float_as_uint(a0)), "r"(__float_as_uint(a1)),
          "r"(__float_as_uint(a2)), "r"(__float_as_uint(a3)),
          "r"(__float_as_uint(b0)), "r"(__float_as_uint(b1)));
}

// ---------------- small kernels ----------------
__global__ void k_zero() {
    int i = blockIdx.x * blockDim.x + threadIdx.x;
    int stride = gridDim.x * blockDim.x;
    for (int j = i; j < N_F; j += stride) { g_deg_se[j] = 0; g_deg_dd[j] = 0; }
    for (int j = i; j < N_H; j += stride) { g_deg_de[j] = 0; g_deg_sd[j] = 0; }
    for (int j = i; j < N_H * TT; j += stride) g_agg[j] = 0.f;
}

__global__ void k_deg(const int* __restrict__ es, const int* __restrict__ ed,
                      const int* __restrict__ ds, const int* __restrict__ dd) {
    int e = blockIdx.x * blockDim.x + threadIdx.x;
    if (e >= NE) return;
    atomicAdd(&g_deg_se[es[e]], 1);
    atomicAdd(&g_deg_de[ed[e]], 1);
    atomicAdd(&g_deg_sd[ds[e]], 1);
    atomicAdd(&g_deg_dd[dd[e]], 1);
}

__global__ void k_enc(const float* __restrict__ feat, const int* __restrict__ es,
                      const int* __restrict__ ed) {
    int e = blockIdx.x * blockDim.x + threadIdx.x;
    if (e >= NE) return;
    int s = es[e], d = ed[e];
    float c = rsqrtf(fmaxf((float)g_deg_se[s], 1.f));
    const float4* fp = reinterpret_cast<const float4*>(feat + (size_t)s * 12);
    float4 v0 = fp[0], v1 = fp[1], v2 = fp[2];
    float vv[12] = {v0.x, v0.y, v0.z, v0.w, v1.x, v1.y, v1.z, v1.w, v2.x, v2.y, v2.z, v2.w};
    float* ap = g_agg + (size_t)d * TT;
#pragma unroll
    for (int t = 0; t < 12; t++) atomicAdd(ap + t, nan0(vv[t]) * c);
}

__global__ void k_hproc(const float* __restrict__ Wenc, const float* __restrict__ benc,
                        const float* __restrict__ Wproc, const float* __restrict__ bproc) {
    __shared__ float sWe[TT * HH], sBe[TT * HH], sWp[TT * TT], sBp[TT];
    int tid = threadIdx.x;
    for (int i = tid; i < TT * HH; i += 256) { sWe[i] = Wenc[i]; sBe[i] = benc[i]; }
    if (tid < TT * TT) sWp[tid] = Wproc[tid];
    if (tid < TT) sBp[tid] = bproc[tid];
    __syncthreads();
    int n = blockIdx.x * 4 + (tid >> 6);
    int h = tid & 63;
    if (n >= N_H) return;
    float cde = rsqrtf(fmaxf((float)g_deg_de[n], 1.f));
    float csd = rsqrtf(fmaxf((float)g_deg_sd[n], 1.f));
    float he[TT];
#pragma unroll
    for (int t = 0; t < TT; t++) {
        float s = g_agg[n * TT + t] * cde;
        he[t] = lrelu(fmaf(s, sWe[t * HH + h], sBe[t * HH + h]));
    }
#pragma unroll
    for (int o = 0; o < TT; o++) {
        float v = sBp[o];
#pragma unroll
        for (int t = 0; t < TT; t++) v = fmaf(he[t], sWp[t * TT + o], v);
        v = fmaxf(v, 0.f) * csd;
        // pair (even,odd) h within the warp -> one half2 store
        float vhi = __shfl_down_sync(0xffffffffu, v, 1);
        if ((h & 1) == 0)
            g_hp[((size_t)o * N_H + n) * 32 + (h >> 1)] = __floats2half2_rn(v, vhi);
    }
}

// --- 3-phase parallel exclusive scan of g_deg_dd -> g_off / g_cur ---
__global__ void k_bsum() {
    __shared__ int sh[32];
    int b = blockIdx.x;
    int i = b * 1024 + threadIdx.x;
    int v = (i < N_F) ? g_deg_dd[i] : 0;
#pragma unroll
    for (int o = 16; o; o >>= 1) v += __shfl_down_sync(0xffffffffu, v, o);
    if ((threadIdx.x & 31) == 0) sh[threadIdx.x >> 5] = v;
    __syncthreads();
    if (threadIdx.x < 32) {
        int x = sh[threadIdx.x];
#pragma unroll
        for (int o = 16; o; o >>= 1) x += __shfl_down_sync(0xffffffffu, x, o);
        if (threadIdx.x == 0) g_bsum[b] = x;
    }
}

__global__ void k_bscan() {   // 1 block, 128 threads, NBLK<=128
    __shared__ int sh[128];
    int i = threadIdx.x;
    int v = (i < NBLK) ? g_bsum[i] : 0;
    sh[i] = v;
    __syncthreads();
    for (int o = 1; o < 128; o <<= 1) {
        int x = (i >= o) ? sh[i - o] : 0;
        __syncthreads();
        sh[i] += x;
        __syncthreads();
    }
    if (i < NBLK) g_bsum[i] = sh[i] - v;   // exclusive
}

__global__ void k_off() {
    __shared__ int sh[1024];
    int b = blockIdx.x, tid = threadIdx.x;
    int i = b * 1024 + tid;
    int v = (i < N_F) ? g_deg_dd[i] : 0;
    sh[tid] = v;
    __syncthreads();
    for (int o = 1; o < 1024; o <<= 1) {
        int x = (tid >= o) ? sh[tid - o] : 0;
        __syncthreads();
        sh[tid] += x;
        __syncthreads();
    }
    int base = g_bsum[b];
    if (i < N_F) {
        g_off[i + 1] = base + sh[tid];
        g_cur[i]     = base + sh[tid] - v;
    }
    if (i == 0) g_off[0] = 0;
}

__global__ void k_fill(const int* __restrict__ ds, const int* __restrict__ dd) {
    int e = blockIdx.x * blockDim.x + threadIdx.x;
    if (e >= NE) return;
    int pos = atomicAdd(&g_cur[dd[e]], 1);
    g_csr[pos] = ds[e];
}

__global__ void k_att(const float* __restrict__ Wlin, const float* __restrict__ blin,
                      const float* __restrict__ Wa1, const float* __restrict__ ba1,
                      const float* __restrict__ Wo) {
    int j = threadIdx.x;
    if (j < AHD) {
        float u = 0.f, c = 0.f;
        for (int h = 0; h < HH; h++) {
            float w = Wa1[h * AHD + j];
            u = fmaf(Wlin[h], w, u);
            c = fmaf(blin[h], w, c);
        }
        g_att[j] = u;
        g_att[AHD + j] = c + ba1[j];
    }
    if (j == 0) {
        float k1 = 0.f, k2 = 0.f;
        for (int h = 0; h < HH; h++) { k1 = fmaf(Wlin[h], Wo[h], k1); k2 = fmaf(blin[h], Wo[h], k2); }
        g_att[2 * AHD] = k1;
        g_att[2 * AHD + 1] = k2;
    }
}

// ---------------- heavy fused phase: 64-row tile, loops all 12 t ----------------
#define SA_S 68
#define SW_S 68
#define SWA_S 136
#define SMEM_PHASE ((64*SA_S + 64*SW_S + 64*SWA_S + 64 + 128 + 128 + 64 + 64) * 4)

__global__ void __launch_bounds__(256)
k_phase(const float* __restrict__ Wdec, const float* __restrict__ bdec,
        const float* __restrict__ Wa1, const float* __restrict__ ba1,
        const float* __restrict__ Wa2, const float* __restrict__ Wo) {
    extern __shared__ float dsm[];
    float* sA   = dsm;
    float* sWd  = sA + 64 * SA_S;
    float* sWa  = sWd + 64 * SW_S;
    float* sB   = sWa + 64 * SWA_S;
    float* sBa1 = sB + 64;
    float* sWa2 = sBa1 + 128;
    float* sWo  = sWa2 + 128;
    float* sSc  = sWo + 64;

    int row0 = blockIdx.x * 64;
    int tid = threadIdx.x;
    int w = tid >> 5, lane = tid & 31;

    // once-per-block weight fills
    for (int i = tid; i < 8192; i += 256) {
        int k = i >> 7, n = i & 127;
        sWa[k * SWA_S + n] = to_tf32(Wa1[i]);
    }
    if (tid < 64) sWo[tid] = Wo[tid];
    else if (tid < 192) { sBa1[tid - 64] = ba1[tid - 64]; sWa2[tid - 64] = Wa2[tid - 64]; }

    // per-warp row ranges (cache offsets & degree norm in registers)
    int beg[8], end[8];
    float cdd[8];
#pragma unroll
    for (int rr = 0; rr < 8; rr++) {
        int f = row0 + w * 8 + rr;
        if (f < N_F) {
            beg[rr] = g_off[f];
            end[rr] = g_off[f + 1];
            cdd[rr] = rsqrtf(fmaxf((float)g_deg_dd[f], 1.f));
        } else { beg[rr] = 0; end[rr] = 0; cdd[rr] = 0.f; }
    }

    int g = lane >> 2, q = lane & 3;
    int r0 = (w & 3) * 16;
    int colsel = w >> 2;

    for (int t = 0; t < TT; t++) {
        __syncthreads();   // prior iteration's reads done before refills
        // per-t fills
        for (int i = tid; i < 4096; i += 256) {
            int k = i >> 6, n = i & 63;
            sWd[k * SW_S + n] = to_tf32(Wdec[t * 4096 + i]);
        }
        if (tid < 64) { sB[tid] = bdec[t * 64 + tid]; sSc[tid] = 0.f; }

        // gather: one 128B fp16 row per edge, 8-way unrolled
        const __half2* hb = g_hp + (size_t)t * N_H * 32;
#pragma unroll
        for (int rr = 0; rr < 8; rr++) {
            float a0 = 0.f, a1v = 0.f;
            int e = beg[rr], en = end[rr];
            for (; e + 8 <= en; e += 8) {
                float2 f0 = __half22float2(hb[(size_t)g_csr[e]     * 32 + lane]);
                float2 f1 = __half22float2(hb[(size_t)g_csr[e + 1] * 32 + lane]);
                float2 f2 = __half22float2(hb[(size_t)g_csr[e + 2] * 32 + lane]);
                float2 f3 = __half22float2(hb[(size_t)g_csr[e + 3] * 32 + lane]);
                float2 f4 = __half22float2(hb[(size_t)g_csr[e + 4] * 32 + lane]);
                float2 f5 = __half22float2(hb[(size_t)g_csr[e + 5] * 32 + lane]);
                float2 f6 = __half22float2(hb[(size_t)g_csr[e + 6] * 32 + lane]);
                float2 f7 = __half22float2(hb[(size_t)g_csr[e + 7] * 32 + lane]);
                a0  += ((f0.x + f1.x) + (f2.x + f3.x)) + ((f4.x + f5.x) + (f6.x + f7.x));
                a1v += ((f0.y + f1.y) + (f2.y + f3.y)) + ((f4.y + f5.y) + (f6.y + f7.y));
            }
            for (; e < en; e++) {
                float2 fx = __half22float2(hb[(size_t)g_csr[e] * 32 + lane]);
                a0 += fx.x;
                a1v += fx.y;
            }
            int r = w * 8 + rr;
            sA[r * SA_S + 2 * lane]     = to_tf32(a0 * cdd[rr]);
            sA[r * SA_S + 2 * lane + 1] = to_tf32(a1v * cdd[rr]);
        }
        __syncthreads();

        // ---- GEMM1: space1 = leaky(A @ Wdec_t + b) ----
        float c1[4][4];
#pragma unroll
        for (int tn = 0; tn < 4; tn++)
#pragma unroll
            for (int i = 0; i < 4; i++) c1[tn][i] = 0.f;
#pragma unroll
        for (int ks = 0; ks < 8; ks++) {
            int k0 = ks * 8;
            float a0 = sA[(r0 + g) * SA_S + k0 + q];
            float a1 = sA[(r0 + g + 8) * SA_S + k0 + q];
            float a2 = sA[(r0 + g) * SA_S + k0 + q + 4];
            float a3 = sA[(r0 + g + 8) * SA_S + k0 + q + 4];
#pragma unroll
            for (int tn = 0; tn < 4; tn++) {
                int nb = colsel * 32 + tn * 8;
                float b0 = sWd[(k0 + q) * SW_S + nb + g];
                float b1 = sWd[(k0 + q + 4) * SW_S + nb + g];
                mma_tf32(c1[tn][0], c1[tn][1], c1[tn][2], c1[tn][3], a0, a1, a2, a3, b0, b1);
            }
        }
        __syncthreads();
        // epilogue: bias + leaky -> space1 into sA
#pragma unroll
        for (int tn = 0; tn < 4; tn++) {
            int col0 = colsel * 32 + tn * 8 + 2 * q;
            sA[(r0 + g) * SA_S + col0]         = to_tf32(lrelu(c1[tn][0] + sB[col0]));
            sA[(r0 + g) * SA_S + col0 + 1]     = to_tf32(lrelu(c1[tn][1] + sB[col0 + 1]));
            sA[(r0 + g + 8) * SA_S + col0]     = to_tf32(lrelu(c1[tn][2] + sB[col0]));
            sA[(r0 + g + 8) * SA_S + col0 + 1] = to_tf32(lrelu(c1[tn][3] + sB[col0 + 1]));
        }
        __syncthreads();

        // s1o = space1 @ Wo (thread per row)
        if (tid < 64) {
            float v = 0.f;
#pragma unroll 8
            for (int k = 0; k < 64; k++) v = fmaf(sA[tid * SA_S + k], sWo[k], v);
            int f = row0 + tid;
            if (f < N_F) g_s1o[t * N_F + f] = v;
        }

        // ---- GEMM2: z = space1 @ Wa1; score1 = tanh(.)@Wa2 ----
        float sc0 = 0.f, sc1 = 0.f;
#pragma unroll
        for (int pass = 0; pass < 2; ++pass) {
            float z[4][4];
#pragma unroll
            for (int tn = 0; tn < 4; tn++)
#pragma unroll
                for (int i = 0; i < 4; i++) z[tn][i] = 0.f;
#pragma unroll
            for (int ks = 0; ks < 8; ks++) {
                int k0 = ks * 8;
                float a0 = sA[(r0 + g) * SA_S + k0 + q];
                float a1 = sA[(r0 + g + 8) * SA_S + k0 + q];
                float a2 = sA[(r0 + g) * SA_S + k0 + q + 4];
                float a3 = sA[(r0 + g + 8) * SA_S + k0 + q + 4];
#pragma unroll
                for (int tn = 0; tn < 4; tn++) {
                    int cb = colsel * 64 + pass * 32 + tn * 8;
                    float b0 = sWa[(k0 + q) * SWA_S + cb + g];
                    float b1 = sWa[(k0 + q + 4) * SWA_S + cb + g];
                    mma_tf32(z[tn][0], z[tn][1], z[tn][2], z[tn][3], a0, a1, a2, a3, b0, b1);
                }
            }
#pragma unroll
            for (int tn = 0; tn < 4; tn++) {
                int col0 = colsel * 64 + pass * 32 + tn * 8 + 2 * q;
                sc0 = fmaf(fast_tanh(z[tn][0] + sBa1[col0]),     sWa2[col0],     sc0);
                sc0 = fmaf(fast_tanh(z[tn][1] + sBa1[col0 + 1]), sWa2[col0 + 1], sc0);
                sc1 = fmaf(fast_tanh(z[tn][2] + sBa1[col0]),     sWa2[col0],     sc1);
                sc1 = fmaf(fast_tanh(z[tn][3] + sBa1[col0 + 1]), sWa2[col0 + 1], sc1);
            }
        }
        sc0 += __shfl_down_sync(0xffffffffu, sc0, 2, 4);
        sc0 += __shfl_down_sync(0xffffffffu, sc0, 1, 4);
        sc1 += __shfl_down_sync(0xffffffffu, sc1, 2, 4);
        sc1 += __shfl_down_sync(0xffffffffu, sc1, 1, 4);
        if (q == 0) {
            atomicAdd(&sSc[r0 + g], sc0);
            atomicAdd(&sSc[r0 + g + 8], sc1);
        }
        __syncthreads();
        if (tid < 64) {
            int f = row0 + tid;
            if (f < N_F) g_score1[t * N_F + f] = sSc[tid];  // b_a2 cancels in softmax
        }
    }
}

// ---------------- fused 12-step scalar recurrence ----------------
__global__ void k_steps(const float* __restrict__ feat, const float* __restrict__ Wa2,
                        const float* __restrict__ bo, float* __restrict__ out) {
    __shared__ float su[128], sc2[128], sw2[128];
    int tid = threadIdx.x;
    if (tid < 128) { su[tid] = g_att[tid]; sc2[tid] = g_att[128 + tid]; sw2[tid] = Wa2[tid]; }
    __syncthreads();
    int f = blockIdx.x * blockDim.x + tid;
    if (f >= N_F) return;
    float y = nan0(feat[(size_t)f * 12 + 11]);
    float k1 = g_att[256], k2 = g_att[257], b0 = bo[0];
#pragma unroll 1
    for (int t = 0; t < TT; t++) {
        float s2a = 0.f, s2b = 0.f;
#pragma unroll 8
        for (int j = 0; j < 128; j += 2) {
            s2a = fmaf(fast_tanh(fmaf(y, su[j],     sc2[j])),     sw2[j],     s2a);
            s2b = fmaf(fast_tanh(fmaf(y, su[j + 1], sc2[j + 1])), sw2[j + 1], s2b);
        }
        float s2 = s2a + s2b;
        float s1 = g_score1[t * N_F + f];
        float mx = fmaxf(s1, s2);
        float e1 = __expf(s1 - mx), e2 = __expf(s2 - mx);
        float a1 = e1 / (e1 + e2);
        float s2o = fmaf(y, k1, k2);
        y = fmaf(a1, g_s1o[t * N_F + f], (1.f - a1) * s2o) + b0;
        out[(size_t)t * N_F + f] = y;
    }
}

// ---------------- launch ----------------
extern "C" void kernel_launch(void* const* d_in, const int* in_sizes, int n_in,
                              void* d_out, int out_size) {
    const float* feat  = (const float*)d_in[0];
    const int*   es    = (const int*)d_in[1];
    const int*   ed    = (const int*)d_in[2];
    const int*   ds    = (const int*)d_in[3];
    const int*   dd    = (const int*)d_in[4];
    const float* Wenc  = (const float*)d_in[5];
    const float* benc  = (const float*)d_in[6];
    const float* Wproc = (const float*)d_in[7];
    const float* bproc = (const float*)d_in[8];
    const float* Wdec  = (const float*)d_in[9];
    const float* bdec  = (const float*)d_in[10];
    const float* Wlin  = (const float*)d_in[11];
    const float* blin  = (const float*)d_in[12];
    const float* Wa1   = (const float*)d_in[13];
    const float* ba1   = (const float*)d_in[14];
    const float* Wa2   = (const float*)d_in[15];
    /* ba2 = d_in[16] cancels in 2-way softmax */
    const float* Wo    = (const float*)d_in[17];
    const float* bo    = (const float*)d_in[18];
    float* out = (float*)d_out;

    cudaFuncSetAttribute(k_phase, cudaFuncAttributeMaxDynamicSharedMemorySize, SMEM_PHASE);

    k_zero<<<512, 256>>>();
    k_deg<<<(NE + 255) / 256, 256>>>(es, ed, ds, dd);
    k_enc<<<(NE + 255) / 256, 256>>>(feat, es, ed);
    k_bsum<<<NBLK, 1024>>>();
    k_bscan<<<1, 128>>>();
    k_off<<<NBLK, 1024>>>();
    k_fill<<<(NE + 255) / 256, 256>>>(ds, dd);
    k_hproc<<<(N_H + 3) / 4, 256>>>(Wenc, benc, Wproc, bproc);
    k_att<<<1, 128>>>(Wlin, blin, Wa1, ba1, Wo);
    k_phase<<<(N_F + 63) / 64, 256, SMEM_PHASE>>>(Wdec, bdec, Wa1, ba1, Wa2, Wo);
    k_steps<<<(N_F + 255) / 256, 256>>>(feat, Wa2, bo, out);
}